// round 12
// baseline (speedup 1.0000x reference)
#include <cuda_runtime.h>
#include <cuda_bf16.h>
#include <cstdint>

// Problem constants (fixed by the reference)
#define B_    4
#define C_    512
#define H_    64
#define W_    208
#define HID_  512
#define DS_   16
#define NREG_ 4

// Stage geometry: 4 regions x 8 column-tiles of 64 (float4 per thread)
#define DTIL_  8
#define COLS_  64                    // columns per tile (16 lanes x float4)
#define NSUB_  32                    // h-subgroups per block (512 thr / 16 lanes)
#define NBLKS_ (NREG_ * DTIL_)       // 32 blocks per stage

// Fused-setup block roles
#define NBLK1_ NBLKS_                          // stage1 blocks [0, 32)
#define NBLKP_ B_                              // perm blocks   [32, 36)
#define NBLK2_ NBLKS_                          // stage2 blocks [36, 68)
#define NBLKF_ (NBLK1_ + NBLKP_ + NBLK2_)      // 68 <= 148 SMs -> co-resident

#define TOTAL_  (B_ * C_ * H_ * W_)            // 27,262,976 elements

// Scratch (device globals; no allocation allowed)
__device__ float g_tmp  [NREG_ * B_ * HID_];  // tmp[r, b, d]
__device__ float g_delta[B_ * NREG_ * C_];    // delta[b, r, c]
__device__ int   g_plab [B_ * W_];            // source col w -> (pos | lab<<16)
__device__ int   g_done = 0;                  // stage1 arrival counter

// Shared GEMV-stage body: out = sum_k vec[b][k] * Wmat[k][col], float4 loads.
template<int NC>
__device__ __forceinline__ void gemv_stage(
        const float* __restrict__ Wmat,       // + r offset applied by caller
        const float (*s_vec)[HID_],           // [B_][HID_] in smem
        float (*s_red)[B_][COLS_],            // [NSUB_][B_][COLS_]
        float* __restrict__ out_base,         // out for (b): out_base + b_stride*b + col
        size_t b_stride,
        int coltile, int tid) {
    const int lane = tid & 15;
    const int hs   = tid >> 4;                // 0..31
    const int col  = coltile * COLS_ + lane * 4;

    const float* wp = Wmat + col;
    float4 acc[B_];
    #pragma unroll
    for (int b = 0; b < B_; ++b) acc[b] = make_float4(0.f, 0.f, 0.f, 0.f);

    #pragma unroll 8
    for (int k = hs; k < HID_; k += NSUB_) {
        const float4 w = *reinterpret_cast<const float4*>(wp + (size_t)k * NC);
        #pragma unroll
        for (int b = 0; b < B_; ++b) {
            const float v = s_vec[b][k];
            acc[b].x = fmaf(v, w.x, acc[b].x);
            acc[b].y = fmaf(v, w.y, acc[b].y);
            acc[b].z = fmaf(v, w.z, acc[b].z);
            acc[b].w = fmaf(v, w.w, acc[b].w);
        }
    }

    #pragma unroll
    for (int b = 0; b < B_; ++b) {
        s_red[hs][b][lane * 4 + 0] = acc[b].x;
        s_red[hs][b][lane * 4 + 1] = acc[b].y;
        s_red[hs][b][lane * 4 + 2] = acc[b].z;
        s_red[hs][b][lane * 4 + 3] = acc[b].w;
    }
    __syncthreads();

    if (tid < B_ * COLS_) {
        const int b = tid >> 6;
        const int c = tid & 63;
        float s = 0.f;
        #pragma unroll
        for (int g = 0; g < NSUB_; ++g) s += s_red[g][b][c];
        out_base[b_stride * b + coltile * COLS_ + c] = s;
    }
}

// ---------------------------------------------------------------------------
// Fused setup kernel, 68 blocks x 512 threads (co-resident in one wave):
//   [0,32):  stage1  tmp[r,b,d] = sum_h tf[r,b,h] * Wv[r,h,d]
//   [32,36): perm    stable counting-sort rank -> packed (pos | lab<<16)
//   [36,68): stage2  delta[b,r,c] = sum_d tmp[r,b,d] * Wo[r,d,c]
// g_done is reset by the gather kernel (stream order => visible next replay).
// ---------------------------------------------------------------------------
__global__ __launch_bounds__(512) void setup_fused(
        const float* __restrict__ text_feat,
        const float* __restrict__ Wv,
        const float* __restrict__ Wo,
        const int*   __restrict__ text_mask) {
    __shared__ float s_vec[B_][HID_];               // 8 KB
    __shared__ float s_red[NSUB_][B_][COLS_];       // 32 KB
    __shared__ int   s_lab[W_];

    const int blk = blockIdx.x;
    const int tid = threadIdx.x;

    if (blk < NBLK1_) {
        // ---------------- stage 1 ----------------
        const int r  = blk / DTIL_;
        const int dt = blk % DTIL_;

        for (int i = tid; i < B_ * HID_; i += 512)
            s_vec[i / HID_][i % HID_] = text_feat[(size_t)r * B_ * HID_ + i];
        __syncthreads();

        gemv_stage<HID_>(Wv + (size_t)r * HID_ * HID_, s_vec, s_red,
                         g_tmp + (size_t)r * B_ * HID_, HID_, dt, tid);
        __syncthreads();
        __threadfence();
        if (tid == 0) atomicAdd(&g_done, 1);

    } else if (blk < NBLK1_ + NBLKP_) {
        // ---------------- perm: inverse LUT (source w -> pos, label) -------
        const int b = blk - NBLK1_;
        const size_t mask_batch_stride = (size_t)(H_ * DS_) * (W_ * DS_);
        if (tid < W_)
            s_lab[tid] = text_mask[b * mask_batch_stride + (size_t)tid * DS_];
        __syncthreads();
        if (tid < W_) {
            const int lab = s_lab[tid];
            int pos = 0;
            #pragma unroll 8
            for (int w2 = 0; w2 < W_; ++w2) {
                const int l2 = s_lab[w2];
                pos += (l2 < lab) || (l2 == lab && w2 < tid);
            }
            g_plab[b * W_ + tid] = pos | ((lab - 1) << 16);
        }

    } else {
        // ---------------- stage 2 ----------------
        const int id = blk - NBLK1_ - NBLKP_;
        const int r  = id / DTIL_;
        const int ct = id % DTIL_;

        if (tid == 0) {
            while (*((volatile int*)&g_done) < NBLK1_) { }
        }
        __syncthreads();
        __threadfence();

        for (int i = tid; i < B_ * HID_; i += 512)
            s_vec[i / HID_][i % HID_] = __ldcg(&g_tmp[(size_t)r * B_ * HID_ + i]);
        __syncthreads();

        gemv_stage<C_>(Wo + (size_t)r * HID_ * C_, s_vec, s_red,
                       g_delta + (size_t)r * C_, (size_t)NREG_ * C_, ct, tid);
    }
}

// ---------------------------------------------------------------------------
// Source-order scatter gather:
//   out[row, pos[w]] = image[row, w] + delta[b, lab[w], c]
// Loads are PERFECTLY linear (image[idx], idx = global linear index).
// Stores scatter, but consecutive same-bucket sources map to consecutive
// output positions -> each warp's 32 stores land in ~4 dense runs
// (~6-10 sectors/warp vs ~60-90 on the old gathered-load side).
// ---------------------------------------------------------------------------
__global__ __launch_bounds__(256) void scatter_add_kernel(
        const float* __restrict__ image, float* __restrict__ out) {
    const int idx = blockIdx.x * blockDim.x + threadIdx.x;
    if (idx >= TOTAL_) return;

    // reset setup's arrival counter for the next graph replay
    if (idx == 0) g_done = 0;

    const int w = idx % W_;                       // source column
    const int b = idx / (C_ * H_ * W_);
    const int c = (idx / (H_ * W_)) % C_;

    const int pl  = g_plab[b * W_ + w];
    const int pos = pl & 0xFFFF;
    const int lab = pl >> 16;

    const float v = __ldg(image + idx) + g_delta[(b * NREG_ + lab) * C_ + c];

    out[idx - w + pos] = v;
}

// ---------------------------------------------------------------------------
// Launch. Input order (metadata): image_feature f32, text_feat f32,
// text_mask i32, Wq f32 (unused), Wk f32 (unused), Wv f32, Wo f32.
// ---------------------------------------------------------------------------
extern "C" void kernel_launch(void* const* d_in, const int* in_sizes, int n_in,
                              void* d_out, int out_size) {
    const float* image     = (const float*)d_in[0];
    const float* text_feat = (const float*)d_in[1];
    const int*   text_mask = (const int*)  d_in[2];
    const float* Wv        = (const float*)d_in[5];
    const float* Wo        = (const float*)d_in[6];
    float* out = (float*)d_out;

    setup_fused<<<NBLKF_, 512>>>(text_feat, Wv, Wo, text_mask);

    const int threads = 256;
    const int blocks = (TOTAL_ + threads - 1) / threads;
    scatter_add_kernel<<<blocks, threads>>>(image, out);
}

// round 13
// speedup vs baseline: 1.8068x; 1.8068x over previous
#include <cuda_runtime.h>
#include <cuda_bf16.h>
#include <cstdint>

// Problem constants (fixed by the reference)
#define B_    4
#define C_    512
#define H_    64
#define W_    208
#define HID_  512
#define DS_   16
#define NREG_ 4

// Stage geometry: 4 regions x 8 column-tiles of 64 (float4 per thread)
#define DTIL_  8
#define COLS_  64                    // columns per tile (16 lanes x float4)
#define NSUB_  32                    // h-subgroups per block (512 thr / 16 lanes)
#define NBLKS_ (NREG_ * DTIL_)       // 32 blocks per stage

// Fused-setup block roles
#define NBLK1_ NBLKS_                          // stage1 blocks [0, 32)
#define NBLKP_ B_                              // perm blocks   [32, 36)
#define NBLK2_ NBLKS_                          // stage2 blocks [36, 68)
#define NBLKF_ (NBLK1_ + NBLKP_ + NBLK2_)      // 68 <= 148 SMs -> co-resident

// Scratch (device globals; no allocation allowed)
__device__ float g_tmp  [NREG_ * B_ * HID_];  // tmp[r, b, d]
__device__ float g_delta[B_ * NREG_ * C_];    // delta[b, r, c]
__device__ int2  g_lut  [B_ * W_];            // out col w -> (src col, reg*C_)
__device__ int   g_done = 0;                  // stage1 arrival counter

// Shared GEMV-stage body: out = sum_k vec[b][k] * Wmat[k][col], float4 loads.
template<int NC>
__device__ __forceinline__ void gemv_stage(
        const float* __restrict__ Wmat,       // + r offset applied by caller
        const float (*s_vec)[HID_],           // [B_][HID_] in smem
        float (*s_red)[B_][COLS_],            // [NSUB_][B_][COLS_]
        float* __restrict__ out_base,         // out for (b): out_base + b_stride*b + col
        size_t b_stride,
        int coltile, int tid) {
    const int lane = tid & 15;
    const int hs   = tid >> 4;                // 0..31
    const int col  = coltile * COLS_ + lane * 4;

    const float* wp = Wmat + col;
    float4 acc[B_];
    #pragma unroll
    for (int b = 0; b < B_; ++b) acc[b] = make_float4(0.f, 0.f, 0.f, 0.f);

    #pragma unroll 8
    for (int k = hs; k < HID_; k += NSUB_) {
        const float4 w = *reinterpret_cast<const float4*>(wp + (size_t)k * NC);
        #pragma unroll
        for (int b = 0; b < B_; ++b) {
            const float v = s_vec[b][k];
            acc[b].x = fmaf(v, w.x, acc[b].x);
            acc[b].y = fmaf(v, w.y, acc[b].y);
            acc[b].z = fmaf(v, w.z, acc[b].z);
            acc[b].w = fmaf(v, w.w, acc[b].w);
        }
    }

    #pragma unroll
    for (int b = 0; b < B_; ++b) {
        s_red[hs][b][lane * 4 + 0] = acc[b].x;
        s_red[hs][b][lane * 4 + 1] = acc[b].y;
        s_red[hs][b][lane * 4 + 2] = acc[b].z;
        s_red[hs][b][lane * 4 + 3] = acc[b].w;
    }
    __syncthreads();

    if (tid < B_ * COLS_) {
        const int b = tid >> 6;
        const int c = tid & 63;
        float s = 0.f;
        #pragma unroll
        for (int g = 0; g < NSUB_; ++g) s += s_red[g][b][c];
        out_base[b_stride * b + coltile * COLS_ + c] = s;
    }
}

// ---------------------------------------------------------------------------
// Fused setup kernel, 68 blocks x 512 threads (co-resident in one wave):
//   [0,32):  stage1  tmp[r,b,d] = sum_h tf[r,b,h] * Wv[r,h,d]
//   [32,36): perm    stable counting-sort rank -> packed (src, reg*C_) LUT
//   [36,68): stage2  delta[b,r,c] = sum_d tmp[r,b,d] * Wo[r,d,c]
// g_done is reset by the gather kernel (stream order => visible next replay).
// ---------------------------------------------------------------------------
__global__ __launch_bounds__(512) void setup_fused(
        const float* __restrict__ text_feat,
        const float* __restrict__ Wv,
        const float* __restrict__ Wo,
        const int*   __restrict__ text_mask) {
    __shared__ float s_vec[B_][HID_];               // 8 KB
    __shared__ float s_red[NSUB_][B_][COLS_];       // 32 KB
    __shared__ int   s_lab[W_];

    const int blk = blockIdx.x;
    const int tid = threadIdx.x;

    if (blk < NBLK1_) {
        // ---------------- stage 1 ----------------
        const int r  = blk / DTIL_;
        const int dt = blk % DTIL_;

        for (int i = tid; i < B_ * HID_; i += 512)
            s_vec[i / HID_][i % HID_] = text_feat[(size_t)r * B_ * HID_ + i];
        __syncthreads();

        gemv_stage<HID_>(Wv + (size_t)r * HID_ * HID_, s_vec, s_red,
                         g_tmp + (size_t)r * B_ * HID_, HID_, dt, tid);
        __syncthreads();
        __threadfence();
        if (tid == 0) atomicAdd(&g_done, 1);

    } else if (blk < NBLK1_ + NBLKP_) {
        // ---------------- perm (stable counting sort via parallel rank) ----
        const int b = blk - NBLK1_;
        const size_t mask_batch_stride = (size_t)(H_ * DS_) * (W_ * DS_);
        if (tid < W_)
            s_lab[tid] = text_mask[b * mask_batch_stride + (size_t)tid * DS_];
        __syncthreads();
        if (tid < W_) {
            const int lab = s_lab[tid];
            int pos = 0;
            #pragma unroll 8
            for (int w2 = 0; w2 < W_; ++w2) {
                const int l2 = s_lab[w2];
                pos += (l2 < lab) || (l2 == lab && w2 < tid);
            }
            // output position pos takes source col tid, region (lab-1)
            g_lut[b * W_ + pos] = make_int2(tid, (lab - 1) * C_);
        }

    } else {
        // ---------------- stage 2 ----------------
        const int id = blk - NBLK1_ - NBLKP_;
        const int r  = id / DTIL_;
        const int ct = id % DTIL_;

        if (tid == 0) {
            while (*((volatile int*)&g_done) < NBLK1_) { }
        }
        __syncthreads();
        __threadfence();

        for (int i = tid; i < B_ * HID_; i += 512)
            s_vec[i / HID_][i % HID_] = __ldcg(&g_tmp[(size_t)r * B_ * HID_ + i]);
        __syncthreads();

        gemv_stage<C_>(Wo + (size_t)r * HID_ * C_, s_vec, s_red,
                       g_delta + (size_t)r * C_, (size_t)NREG_ * C_, ct, tid);
    }
}

// ---------------------------------------------------------------------------
// Gather v3: each thread produces the same float4 (w4) for TWO adjacent
// h-rows (same b, c => identical LUT and delta values reused):
//   - LUT loads + index ALU halved per output
//   - delta loads halved per output
//   - 8 independent gathered loads in flight per thread (better overlap)
// Stores remain two fully-coalesced float4 streams.
// ---------------------------------------------------------------------------
#define ROW4_   (W_ / 4)                         // 52
#define H2_     (H_ / 2)                         // 32
#define TOTALP_ (B_ * C_ * H2_ * ROW4_)          // 3,407,872 pairs

__global__ __launch_bounds__(256) void gather_add_kernel(
        const float* __restrict__ image, float* __restrict__ out) {
    const int idx = blockIdx.x * blockDim.x + threadIdx.x;
    if (idx >= TOTALP_) return;

    // reset setup's arrival counter for the next graph replay
    if (idx == 0) g_done = 0;

    const int w4 = idx % ROW4_;
    const int rp = idx / ROW4_;                   // (b, c, h2)
    const int h2 = rp & (H2_ - 1);
    const int c  = (rp >> 5) & (C_ - 1);
    const int b  = rp >> 14;                      // / (C_ * H2_)
    const int w  = w4 * 4;

    const int row = ((b * C_ + c) << 6) + h2 * 2; // (b*C + c)*H + 2*h2

    // packed LUT: 4 x int2 = two int4 loads
    const int4* lutp = reinterpret_cast<const int4*>(&g_lut[b * W_ + w]);
    const int4 p01 = lutp[0];                     // (src0, roff0, src1, roff1)
    const int4 p23 = lutp[1];                     // (src2, roff2, src3, roff3)

    const float* drow = g_delta + b * (NREG_ * C_) + c;
    const float d0 = drow[p01.y];
    const float d1 = drow[p01.w];
    const float d2 = drow[p23.y];
    const float d3 = drow[p23.w];

    const float* imrow0 = image + (size_t)row * W_;
    const float* imrow1 = imrow0 + W_;

    float4 o0, o1;
    o0.x = __ldg(imrow0 + p01.x) + d0;
    o0.y = __ldg(imrow0 + p01.z) + d1;
    o0.z = __ldg(imrow0 + p23.x) + d2;
    o0.w = __ldg(imrow0 + p23.z) + d3;

    o1.x = __ldg(imrow1 + p01.x) + d0;
    o1.y = __ldg(imrow1 + p01.z) + d1;
    o1.z = __ldg(imrow1 + p23.x) + d2;
    o1.w = __ldg(imrow1 + p23.z) + d3;

    float4* out4 = reinterpret_cast<float4*>(out);
    out4[(size_t)row * ROW4_ + w4]         = o0;
    out4[(size_t)(row + 1) * ROW4_ + w4]   = o1;
}

// ---------------------------------------------------------------------------
// Launch. Input order (metadata): image_feature f32, text_feat f32,
// text_mask i32, Wq f32 (unused), Wk f32 (unused), Wv f32, Wo f32.
// ---------------------------------------------------------------------------
extern "C" void kernel_launch(void* const* d_in, const int* in_sizes, int n_in,
                              void* d_out, int out_size) {
    const float* image     = (const float*)d_in[0];
    const float* text_feat = (const float*)d_in[1];
    const int*   text_mask = (const int*)  d_in[2];
    const float* Wv        = (const float*)d_in[5];
    const float* Wo        = (const float*)d_in[6];
    float* out = (float*)d_out;

    setup_fused<<<NBLKF_, 512>>>(text_feat, Wv, Wo, text_mask);

    const int threads = 256;
    const int blocks = (TOTALP_ + threads - 1) / threads;
    gather_add_kernel<<<blocks, threads>>>(image, out);
}

// round 14
// speedup vs baseline: 1.8756x; 1.0381x over previous
#include <cuda_runtime.h>
#include <cuda_bf16.h>
#include <cstdint>

// Problem constants (fixed by the reference)
#define B_    4
#define C_    512
#define H_    64
#define W_    208
#define HID_  512
#define DS_   16
#define NREG_ 4

// Stage geometry: 4 regions x 8 column-tiles of 64 (float4 per thread)
#define DTIL_  8
#define COLS_  64                    // columns per tile (16 lanes x float4)
#define NSUB_  32                    // h-subgroups per block (512 thr / 16 lanes)
#define NBLKS_ (NREG_ * DTIL_)       // 32 blocks per stage

// Fused-setup block roles
#define NBLK1_ NBLKS_                          // stage1 blocks [0, 32)
#define NBLKP_ B_                              // perm blocks   [32, 36)
#define NBLK2_ NBLKS_                          // stage2 blocks [36, 68)
#define NBLKF_ (NBLK1_ + NBLKP_ + NBLK2_)      // 68 <= 148 SMs -> co-resident

// Scratch (device globals; no allocation allowed)
__device__ float g_tmp  [NREG_ * B_ * HID_];  // tmp[r, b, d]
__device__ float g_delta[B_ * NREG_ * C_];    // delta[b, r, c]
__device__ int2  g_lut  [B_ * W_];            // out col w -> (src col, reg*C_)
__device__ int   g_done = 0;                  // stage1 arrival counter

// Shared GEMV-stage body: out = sum_k vec[b][k] * Wmat[k][col], float4 loads.
template<int NC>
__device__ __forceinline__ void gemv_stage(
        const float* __restrict__ Wmat,       // + r offset applied by caller
        const float (*s_vec)[HID_],           // [B_][HID_] in smem
        float (*s_red)[B_][COLS_],            // [NSUB_][B_][COLS_]
        float* __restrict__ out_base,         // out for (b): out_base + b_stride*b + col
        size_t b_stride,
        int coltile, int tid) {
    const int lane = tid & 15;
    const int hs   = tid >> 4;                // 0..31
    const int col  = coltile * COLS_ + lane * 4;

    const float* wp = Wmat + col;
    float4 acc[B_];
    #pragma unroll
    for (int b = 0; b < B_; ++b) acc[b] = make_float4(0.f, 0.f, 0.f, 0.f);

    #pragma unroll 8
    for (int k = hs; k < HID_; k += NSUB_) {
        const float4 w = *reinterpret_cast<const float4*>(wp + (size_t)k * NC);
        #pragma unroll
        for (int b = 0; b < B_; ++b) {
            const float v = s_vec[b][k];
            acc[b].x = fmaf(v, w.x, acc[b].x);
            acc[b].y = fmaf(v, w.y, acc[b].y);
            acc[b].z = fmaf(v, w.z, acc[b].z);
            acc[b].w = fmaf(v, w.w, acc[b].w);
        }
    }

    #pragma unroll
    for (int b = 0; b < B_; ++b) {
        s_red[hs][b][lane * 4 + 0] = acc[b].x;
        s_red[hs][b][lane * 4 + 1] = acc[b].y;
        s_red[hs][b][lane * 4 + 2] = acc[b].z;
        s_red[hs][b][lane * 4 + 3] = acc[b].w;
    }
    __syncthreads();

    if (tid < B_ * COLS_) {
        const int b = tid >> 6;
        const int c = tid & 63;
        float s = 0.f;
        #pragma unroll
        for (int g = 0; g < NSUB_; ++g) s += s_red[g][b][c];
        out_base[b_stride * b + coltile * COLS_ + c] = s;
    }
}

// ---------------------------------------------------------------------------
// Fused setup kernel, 68 blocks x 512 threads (co-resident in one wave):
//   [0,32):  stage1  tmp[r,b,d] = sum_h tf[r,b,h] * Wv[r,h,d]
//   [32,36): perm    stable counting-sort rank -> packed (src, reg*C_) LUT
//   [36,68): stage2  delta[b,r,c] = sum_d tmp[r,b,d] * Wo[r,d,c]
// g_done is reset by the gather kernel (stream order => visible next replay).
// ---------------------------------------------------------------------------
__global__ __launch_bounds__(512) void setup_fused(
        const float* __restrict__ text_feat,
        const float* __restrict__ Wv,
        const float* __restrict__ Wo,
        const int*   __restrict__ text_mask) {
    __shared__ float s_vec[B_][HID_];               // 8 KB
    __shared__ float s_red[NSUB_][B_][COLS_];       // 32 KB
    __shared__ int   s_lab[W_];

    const int blk = blockIdx.x;
    const int tid = threadIdx.x;

    if (blk < NBLK1_) {
        // ---------------- stage 1 ----------------
        const int r  = blk / DTIL_;
        const int dt = blk % DTIL_;

        for (int i = tid; i < B_ * HID_; i += 512)
            s_vec[i / HID_][i % HID_] = text_feat[(size_t)r * B_ * HID_ + i];
        __syncthreads();

        gemv_stage<HID_>(Wv + (size_t)r * HID_ * HID_, s_vec, s_red,
                         g_tmp + (size_t)r * B_ * HID_, HID_, dt, tid);
        __syncthreads();
        __threadfence();
        if (tid == 0) atomicAdd(&g_done, 1);

    } else if (blk < NBLK1_ + NBLKP_) {
        // ---------------- perm (stable counting sort via parallel rank) ----
        const int b = blk - NBLK1_;
        const size_t mask_batch_stride = (size_t)(H_ * DS_) * (W_ * DS_);
        if (tid < W_)
            s_lab[tid] = text_mask[b * mask_batch_stride + (size_t)tid * DS_];
        __syncthreads();
        if (tid < W_) {
            const int lab = s_lab[tid];
            int pos = 0;
            #pragma unroll 8
            for (int w2 = 0; w2 < W_; ++w2) {
                const int l2 = s_lab[w2];
                pos += (l2 < lab) || (l2 == lab && w2 < tid);
            }
            // output position pos takes source col tid, region (lab-1)
            g_lut[b * W_ + pos] = make_int2(tid, (lab - 1) * C_);
        }

    } else {
        // ---------------- stage 2 ----------------
        const int id = blk - NBLK1_ - NBLKP_;
        const int r  = id / DTIL_;
        const int ct = id % DTIL_;

        if (tid == 0) {
            while (*((volatile int*)&g_done) < NBLK1_) { }
        }
        __syncthreads();
        __threadfence();

        for (int i = tid; i < B_ * HID_; i += 512)
            s_vec[i / HID_][i % HID_] = __ldcg(&g_tmp[(size_t)r * B_ * HID_ + i]);
        __syncthreads();

        gemv_stage<C_>(Wo + (size_t)r * HID_ * C_, s_vec, s_red,
                       g_delta + (size_t)r * C_, (size_t)NREG_ * C_, ct, tid);
    }
}

// ---------------------------------------------------------------------------
// Gather v4: each thread produces the same float4 (w4) for FOUR adjacent
// h-rows (same b, c => identical LUT and delta values reused 4x):
//   - LUT loads + index ALU quartered per output
//   - delta loads quartered per output
//   - 16 independent gathered loads in flight per thread
// Stores remain four fully-coalesced float4 streams.
// ---------------------------------------------------------------------------
#define ROW4_   (W_ / 4)                         // 52
#define H4_     (H_ / 4)                         // 16
#define TOTALQ_ (B_ * C_ * H4_ * ROW4_)          // 1,703,936 quads

__global__ __launch_bounds__(256) void gather_add_kernel(
        const float* __restrict__ image, float* __restrict__ out) {
    const int idx = blockIdx.x * blockDim.x + threadIdx.x;
    if (idx >= TOTALQ_) return;

    // reset setup's arrival counter for the next graph replay
    if (idx == 0) g_done = 0;

    const int w4 = idx % ROW4_;
    const int rq = idx / ROW4_;                   // (b, c, h4)
    const int h4 = rq & (H4_ - 1);
    const int c  = (rq >> 4) & (C_ - 1);
    const int b  = rq >> 13;                      // / (C_ * H4_)
    const int w  = w4 * 4;

    const int row = ((b * C_ + c) << 6) + h4 * 4; // (b*C + c)*H + 4*h4

    // packed LUT: 4 x int2 = two int4 loads
    const int4* lutp = reinterpret_cast<const int4*>(&g_lut[b * W_ + w]);
    const int4 p01 = lutp[0];                     // (src0, roff0, src1, roff1)
    const int4 p23 = lutp[1];                     // (src2, roff2, src3, roff3)

    const float* drow = g_delta + b * (NREG_ * C_) + c;
    const float d0 = __ldg(drow + p01.y);
    const float d1 = __ldg(drow + p01.w);
    const float d2 = __ldg(drow + p23.y);
    const float d3 = __ldg(drow + p23.w);

    const float* imrow = image + (size_t)row * W_;
    float4* out4 = reinterpret_cast<float4*>(out);

    float4 o[4];
    #pragma unroll
    for (int rr = 0; rr < 4; ++rr) {
        const float* im = imrow + rr * W_;
        o[rr].x = __ldg(im + p01.x) + d0;
        o[rr].y = __ldg(im + p01.z) + d1;
        o[rr].z = __ldg(im + p23.x) + d2;
        o[rr].w = __ldg(im + p23.z) + d3;
    }
    #pragma unroll
    for (int rr = 0; rr < 4; ++rr)
        out4[(size_t)(row + rr) * ROW4_ + w4] = o[rr];
}

// ---------------------------------------------------------------------------
// Launch. Input order (metadata): image_feature f32, text_feat f32,
// text_mask i32, Wq f32 (unused), Wk f32 (unused), Wv f32, Wo f32.
// ---------------------------------------------------------------------------
extern "C" void kernel_launch(void* const* d_in, const int* in_sizes, int n_in,
                              void* d_out, int out_size) {
    const float* image     = (const float*)d_in[0];
    const float* text_feat = (const float*)d_in[1];
    const int*   text_mask = (const int*)  d_in[2];
    const float* Wv        = (const float*)d_in[5];
    const float* Wo        = (const float*)d_in[6];
    float* out = (float*)d_out;

    setup_fused<<<NBLKF_, 512>>>(text_feat, Wv, Wo, text_mask);

    const int threads = 256;
    const int blocks = (TOTALQ_ + threads - 1) / threads;
    gather_add_kernel<<<blocks, threads>>>(image, out);
}